// round 4
// baseline (speedup 1.0000x reference)
#include <cuda_runtime.h>
#include <math.h>

// ---------------- problem constants ----------------
#define Bb   16
#define Ll   336
#define Hh   192
#define Cc   862
#define Kk   8
#define Ss   8
#define FREQ 97            // H/2 + 1
#define NF   17            // 2K+1
#define OUTD 1649          // FREQ*NF
#define SEQ  528           // L+H
#define BC   (Bb*Cc)       // 13792
#define MIXF 291           // 3*FREQ
#define KD   72            // 64 (s,k) + 8 (s) rows
#define KTOT (2*MIXF)      // 582
#define NOUT (2*FREQ)      // 194

// ---------------- scratch (static device globals; no allocation) ----------------
__device__ float g_seq   [BC*SEQ];        // normalized [xn | yn] per channel (29.1 MB)
__device__ float g_mu    [BC];
__device__ float g_std   [BC];
__device__ float g_coeff [BC*KD];         // p[s]*cf[k] (64) then p[s] (8)
__device__ float g_sgn   [BC*Kk];
__device__ float g_filt  [(size_t)BC*OUTD]; // 91 MB
__device__ float g_mixin [BC*KTOT];       // [re(291) | im(291)] per bc
__device__ float g_mixout[BC*NOUT];       // [re(97) | im(97)] per bc
__device__ float g_V     [KTOT*NOUT];     // folded complex mix weight as real matrix

// ================= K1: normalize + classifier + softmaxes =================
__global__ void __launch_bounds__(192) k1(
                   const float* __restrict__ x,  const float* __restrict__ yh,
                   const float* __restrict__ r_in, const float* __restrict__ temp,
                   const float* __restrict__ cw, const float* __restrict__ bst,
                   const float* __restrict__ sb)
{
    int bc = blockIdx.x;
    int b = bc / Cc, c = bc % Cc;
    __shared__ float xs[Ll];
    __shared__ float rb[64];
    __shared__ float lg[Ss];
    __shared__ float st2[2];
    int tid  = threadIdx.x;            // 192 threads
    int lane = tid & 31, wp = tid >> 5;

    float s0 = 0.f, s1 = 0.f;
    for (int l = tid; l < Ll; l += 192) {
        float v = x[(b*Ll + l)*Cc + c];
        xs[l] = v; s0 += v; s1 += v*v;
    }
    for (int o = 16; o; o >>= 1) {
        s0 += __shfl_down_sync(0xffffffffu, s0, o);
        s1 += __shfl_down_sync(0xffffffffu, s1, o);
    }
    if (lane == 0) { rb[wp] = s0; rb[8+wp] = s1; }
    __syncthreads();
    if (tid == 0) {
        float a = 0.f, q = 0.f;
        for (int w = 0; w < 6; w++) { a += rb[w]; q += rb[8+w]; }
        float mu  = a * (1.f/Ll);
        float var = q * (1.f/Ll) - mu*mu;
        float sd  = sqrtf(var + 1e-8f);
        st2[0] = mu; st2[1] = sd;
        g_mu[bc] = mu; g_std[bc] = sd;
    }
    __syncthreads();
    float mu = st2[0], rs = 1.f / st2[1];
    for (int l = tid; l < Ll; l += 192)
        g_seq[bc*SEQ + l] = (xs[l] - mu) * rs;
    for (int h = tid; h < Hh; h += 192) {
        float v = yh[(b*Hh + h)*Cc + c];
        g_seq[bc*SEQ + Ll + h] = (v - mu) * rs;
    }

    // classifier logits: sum_l xt[l]*cw[s][l]  (raw xt!)
    float acc[Ss];
#pragma unroll
    for (int s = 0; s < Ss; s++) acc[s] = 0.f;
    for (int l = tid; l < Ll; l += 192) {
        float xv = xs[l];
#pragma unroll
        for (int s = 0; s < Ss; s++) acc[s] += xv * cw[s*Ll + l];
    }
#pragma unroll
    for (int s = 0; s < Ss; s++)
        for (int o = 16; o; o >>= 1)
            acc[s] += __shfl_down_sync(0xffffffffu, acc[s], o);
    __syncthreads();
    if (lane == 0) {
#pragma unroll
        for (int s = 0; s < Ss; s++) rb[wp*8 + s] = acc[s];
    }
    __syncthreads();
    if (tid < Ss) {
        float t = 0.f;
        for (int w = 0; w < 6; w++) t += rb[w*8 + tid];
        lg[tid] = t + sb[tid] + bst[c*Ss + tid];
    }
    __syncthreads();
    if (tid == 0) {
        float mx = lg[0];
        for (int s = 1; s < Ss; s++) mx = fmaxf(mx, lg[s]);
        float p[Ss], se = 0.f;
        for (int s = 0; s < Ss; s++) { p[s] = expf(lg[s] - mx); se += p[s]; }
        float inv = 1.f / se;
        for (int s = 0; s < Ss; s++) p[s] *= inv;

        float T = temp[0], iT = 1.f / T;
        float z[Kk+1], sg[Kk];
        z[0] = iT;
        float zm = z[0];
        for (int k = 0; k < Kk; k++) {
            float r = r_in[bc*Kk + k];
            sg[k] = (r > 0.f) ? 1.f : ((r < 0.f) ? -1.f : 0.f);
            z[k+1] = fabsf(r) * iT;
            zm = fmaxf(zm, z[k+1]);
        }
        float zs = 0.f, e[Kk+1];
        for (int i = 0; i <= Kk; i++) { e[i] = expf(z[i] - zm); zs += e[i]; }
        float izs = 1.f / zs;
        float cf[Kk];
        for (int k = 0; k < Kk; k++) cf[k] = e[k+1] * izs;

        float* co = &g_coeff[bc*KD];
        for (int s = 0; s < Ss; s++)
            for (int k = 0; k < Kk; k++) co[s*Kk + k] = p[s]*cf[k];
        for (int s = 0; s < Ss; s++) co[64 + s] = p[s];
        for (int k = 0; k < Kk; k++) g_sgn[bc*Kk + k] = sg[k];
    }
}

// ================= K0: build folded complex mix weight V[582][194] =================
__global__ void k0(const float* __restrict__ wr, const float* __restrict__ wi)
{
    int i = blockIdx.x * blockDim.x + threadIdx.x;
    if (i >= KTOT*NOUT) return;
    int f  = i / NOUT;
    int on = i % NOUT;
    int fr = (f < MIXF) ? f : f - MIXF;
    float v;
    if (on < FREQ) {                                  // real output rows
        v = (f < MIXF) ? wr[on*MIXF + fr] : -wi[on*MIXF + fr];
    } else {                                          // imag output rows
        int o = on - FREQ;
        v = (f < MIXF) ? wi[o*MIXF + fr] : wr[o*MIXF + fr];
    }
    g_V[i] = v;
}

// ================= K2: filt = coeff[72] @ W72[72,1649] =================
#define K2_TN 128
#define K2_TM 32
__global__ void __launch_bounds__(128) k2(
                   const float* __restrict__ mhw, const float* __restrict__ mhb)
{
    __shared__ float Wsh[KD*K2_TN];   // 36 KB
    __shared__ float Csh[KD*36];      // padded stride 36 for float4 + banks
    int tid = threadIdx.x;            // 128
    int o0 = blockIdx.x * K2_TN;
    int m0 = blockIdx.y * K2_TM;
    int o  = o0 + tid;

    for (int j = 0; j < KD; j++) {
        float v = 0.f;
        if (o < OUTD) {
            if (j < 64) v = mhw[(j >> 3)*(Kk*OUTD) + (j & 7)*OUTD + o];
            else        v = mhb[(j - 64)*OUTD + o];
        }
        Wsh[j*K2_TN + tid] = v;
    }
    for (int idx = tid; idx < K2_TM*KD; idx += 128) {
        int m = idx / KD, j = idx % KD;      // coalesced over j in g_coeff row
        Csh[j*36 + m] = g_coeff[(m0 + m)*KD + j];
    }
    __syncthreads();

    float accv[K2_TM];
#pragma unroll
    for (int m = 0; m < K2_TM; m++) accv[m] = 0.f;
    for (int j = 0; j < KD; j++) {
        float w = Wsh[j*K2_TN + tid];
        const float4* cp = (const float4*)(&Csh[j*36]);
#pragma unroll
        for (int mm = 0; mm < 8; mm++) {
            float4 cv = cp[mm];
            accv[4*mm+0] += cv.x * w;
            accv[4*mm+1] += cv.y * w;
            accv[4*mm+2] += cv.z * w;
            accv[4*mm+3] += cv.w * w;
        }
    }
    if (o < OUTD) {
#pragma unroll
        for (int m = 0; m < K2_TM; m++)
            g_filt[(size_t)(m0 + m)*OUTD + o] = accv[m];
    }
}

// ================= K3: gather + 9 folded DFTs + mix_in =================
__global__ void __launch_bounds__(128) k3(
                   const int* __restrict__ lids, const int* __restrict__ shf)
{
    int bc = blockIdx.x;
    int b = bc / Cc;
    __shared__ float  sq[9][Hh];
    __shared__ float2 fad[9][96];       // (x[h]+x[192-h], x[h]-x[192-h]), h=1..95
    __shared__ float2 ctab[Hh];         // (cos, sin)(2*pi*j/192)
    __shared__ float  x0s[9], x96s[9];
    __shared__ float  Xre[9][FREQ], Xim[9][FREQ];
    __shared__ float  flt[NF*FREQ];
    int tid = threadIdx.x;              // 128

    for (int j = tid; j < Hh; j += 128) {
        float sn, csv;
        sincospif(j * (2.0f/Hh), &sn, &csv);
        ctab[j] = make_float2(csv, sn);
    }
    for (int t = 0; t < Kk; t++) {
        int   ld = lids[bc*Kk + t];
        int   sh = shf [bc*Kk + t];
        float sg = g_sgn[bc*Kk + t];
        const float* src = &g_seq[(b*Cc + ld)*SEQ + Ll - sh];
        for (int h = tid; h < Hh; h += 128) sq[t][h] = src[h] * sg;
    }
    for (int h = tid; h < Hh; h += 128) sq[8][h] = g_seq[bc*SEQ + Ll + h];
    for (int i = tid; i < NF*FREQ; i += 128) flt[i] = g_filt[(size_t)bc*OUTD + i];
    __syncthreads();

    for (int i = tid; i < 9*95; i += 128) {
        int t = i / 95, h = i % 95 + 1;
        float u = sq[t][h], v = sq[t][Hh - h];
        fad[t][h] = make_float2(u + v, u - v);
    }
    if (tid < 9) { x0s[tid] = sq[tid][0]; x96s[tid] = sq[tid][96]; }
    __syncthreads();

    // forward DFT, transform pairs (0,1)(2,3)(4,5)(6,7) share twiddle loads
    for (int j = tid; j < 4*FREQ; j += 128) {
        int pi = j / FREQ, f = j - pi*FREQ;
        int t0 = 2*pi, t1 = t0 + 1;
        float sgf = (f & 1) ? -1.f : 1.f;
        float re0 = x0s[t0] + sgf*x96s[t0];
        float re1 = x0s[t1] + sgf*x96s[t1];
        float im0 = 0.f, im1 = 0.f;
        int idx = 0;
#pragma unroll 5
        for (int h = 1; h <= 95; h++) {
            idx += f; if (idx >= Hh) idx -= Hh;
            float2 cs = ctab[idx];
            float2 p0 = fad[t0][h];
            float2 p1 = fad[t1][h];
            re0 += p0.x*cs.x; im0 += p0.y*cs.y;
            re1 += p1.x*cs.x; im1 += p1.y*cs.y;
        }
        Xre[t0][f] = re0; Xim[t0][f] = -im0;
        Xre[t1][f] = re1; Xim[t1][f] = -im1;
    }
    // transform 8 (yn) solo
    for (int f = tid; f < FREQ; f += 128) {
        float sgf = (f & 1) ? -1.f : 1.f;
        float re = x0s[8] + sgf*x96s[8];
        float im = 0.f;
        int idx = 0;
#pragma unroll 5
        for (int h = 1; h <= 95; h++) {
            idx += f; if (idx >= Hh) idx -= Hh;
            float2 cs = ctab[idx];
            float2 p0 = fad[8][h];
            re += p0.x*cs.x; im += p0.y*cs.y;
        }
        Xre[8][f] = re; Xim[8][f] = -im;
    }
    __syncthreads();

    // mix_in = [lead_sum | diff_sum | self]  (re then im halves)
    for (int f = tid; f < FREQ; f += 128) {
        float yre = Xre[8][f], yim = Xim[8][f];
        float Are = 0.f, Aim = 0.f, Dre = 0.f, Dim = 0.f;
#pragma unroll
        for (int k = 0; k < Kk; k++) {
            float sre = Xre[k][f], sim = Xim[k][f];
            float fl = flt[k*FREQ + f];
            float fd = flt[(Kk + k)*FREQ + f];
            Are += sre*fl;          Aim += sim*fl;
            Dre += (sre - yre)*fd;  Dim += (sim - yim)*fd;
        }
        float fs = flt[2*Kk*FREQ + f];
        float* mo = &g_mixin[bc*KTOT];
        mo[f]                = Are;
        mo[FREQ + f]         = Dre;
        mo[2*FREQ + f]       = yre*fs;
        mo[MIXF + f]         = Aim;
        mo[MIXF + FREQ + f]  = Dim;
        mo[MIXF + 2*FREQ + f]= yim*fs;
    }
}

// ================= K4: mix_out = mix_in[582] @ V[582,194] + bias =================
#define K4_TN 128
#define K4_TM 32
#define K4_TK 32
__global__ void __launch_bounds__(128) k4(
                   const float* __restrict__ br, const float* __restrict__ bi)
{
    __shared__ float Vsh[K4_TK*K4_TN];   // 16 KB
    __shared__ float Ish[K4_TK*36];      // padded
    int tid = threadIdx.x;               // 128
    int n0 = blockIdx.x * K4_TN;
    int m0 = blockIdx.y * K4_TM;
    int on = n0 + tid;

    float accv[K4_TM];
#pragma unroll
    for (int m = 0; m < K4_TM; m++) accv[m] = 0.f;

    for (int kc = 0; kc < KTOT; kc += K4_TK) {
        __syncthreads();
        for (int kk = 0; kk < K4_TK; kk++) {
            int k = kc + kk;
            Vsh[kk*K4_TN + tid] = (k < KTOT && on < NOUT) ? g_V[k*NOUT + on] : 0.f;
        }
        for (int idx = tid; idx < K4_TM*K4_TK; idx += 128) {
            int m = idx / K4_TK, kk = idx % K4_TK;  // coalesced over kk
            int k = kc + kk;
            Ish[kk*36 + m] = (k < KTOT) ? g_mixin[(m0 + m)*KTOT + k] : 0.f;
        }
        __syncthreads();
        for (int kk = 0; kk < K4_TK; kk++) {
            float w = Vsh[kk*K4_TN + tid];
            const float4* ip = (const float4*)(&Ish[kk*36]);
#pragma unroll
            for (int mm = 0; mm < 8; mm++) {
                float4 iv = ip[mm];
                accv[4*mm+0] += iv.x * w;
                accv[4*mm+1] += iv.y * w;
                accv[4*mm+2] += iv.z * w;
                accv[4*mm+3] += iv.w * w;
            }
        }
    }
    if (on < NOUT) {
        float bias = (on < FREQ) ? br[on] : bi[on - FREQ];
#pragma unroll
        for (int m = 0; m < K4_TM; m++)
            g_mixout[(m0 + m)*NOUT + on] = accv[m] + bias;
    }
}

// ================= K5: irfft + denormalize + transposed store =================
__global__ void __launch_bounds__(192) k5(float* __restrict__ out)
{
    int bc = blockIdx.x;
    int b = bc / Cc, c = bc % Cc;
    __shared__ float2 mo[FREQ];
    __shared__ float2 ctab[Hh];
    int tid = threadIdx.x;               // 192
    for (int j = tid; j < Hh; j += 192) {
        float sn, csv;
        sincospif(j * (2.0f/Hh), &sn, &csv);
        ctab[j] = make_float2(csv, sn);
    }
    for (int i = tid; i < FREQ; i += 192)
        mo[i] = make_float2(g_mixout[bc*NOUT + i], g_mixout[bc*NOUT + FREQ + i]);
    __syncthreads();

    int h = tid;                          // one output sample per thread
    float R0 = mo[0].x, R96 = mo[96].x;   // imag of DC/Nyquist ignored (pocketfft c2r)
    float acc = 0.f;
    int idx = 0;
#pragma unroll 5
    for (int f = 1; f <= 95; f++) {
        idx += h; if (idx >= Hh) idx -= Hh;
        float2 cs = ctab[idx];
        float2 X  = mo[f];
        acc += X.x*cs.x;      // Re X * cos
        acc -= X.y*cs.y;      // - Im X * sin   (e^{+i theta})
    }
    float xh = (R0 + ((h & 1) ? -R96 : R96) + 2.f*acc) * (1.f/Hh);
    float yn = g_seq[bc*SEQ + Ll + h];
    out[(b*Hh + h)*Cc + c] = (yn + xh) * g_std[bc] + g_mu[bc];
}

// ================= launcher =================
extern "C" void kernel_launch(void* const* d_in, const int* in_sizes, int n_in,
                              void* d_out, int out_size)
{
    const float* x   = (const float*)d_in[0];
    const float* yh  = (const float*)d_in[1];
    const float* r   = (const float*)d_in[2];
    const float* tmp = (const float*)d_in[3];
    const float* cw  = (const float*)d_in[4];
    const float* bst = (const float*)d_in[5];
    const float* sb  = (const float*)d_in[6];
    const float* mhw = (const float*)d_in[7];
    const float* mhb = (const float*)d_in[8];
    const float* mwr = (const float*)d_in[9];
    const float* mwi = (const float*)d_in[10];
    const float* mbr = (const float*)d_in[11];
    const float* mbi = (const float*)d_in[12];
    const int*   lid = (const int*)d_in[13];
    const int*   shf = (const int*)d_in[14];
    float* out = (float*)d_out;

    k1<<<BC, 192>>>(x, yh, r, tmp, cw, bst, sb);
    k0<<<(KTOT*NOUT + 255)/256, 256>>>(mwr, mwi);
    k2<<<dim3((OUTD + K2_TN - 1)/K2_TN, BC/K2_TM), 128>>>(mhw, mhb);
    k3<<<BC, 128>>>(lid, shf);
    k4<<<dim3((NOUT + K4_TN - 1)/K4_TN, BC/K4_TM), 128>>>(mbr, mbi);
    k5<<<BC, 192>>>(out);
}

// round 7
// speedup vs baseline: 1.5970x; 1.5970x over previous
#include <cuda_runtime.h>
#include <math.h>

// ---------------- problem constants ----------------
#define Bb   16
#define Ll   336
#define Hh   192
#define Cc   862
#define Kk   8
#define Ss   8
#define FREQ 97            // H/2 + 1
#define NF   17            // 2K+1
#define OUTD 1649          // FREQ*NF
#define SEQ  528           // L+H
#define BC   (Bb*Cc)       // 13792
#define MIXF 291           // 3*FREQ
#define KD   72            // 64 (s,k) + 8 (s) rows
#define KTOT (2*MIXF)      // 582
#define NOUT (2*FREQ)      // 194

// ---------------- scratch (static device globals; no allocation) ----------------
__device__ float g_xt    [BC*Ll];         // transposed x  (B,C,L)
__device__ float g_yt    [BC*Hh];         // transposed y_hat (B,C,H)
__device__ float g_seq   [BC*SEQ];        // normalized [xn | yn] per channel
__device__ float g_mu    [BC];
__device__ float g_std   [BC];
__device__ float g_coeff [BC*KD];         // p[s]*cf[k] (64) then p[s] (8)
__device__ float g_sgn   [BC*Kk];
__device__ float g_filt  [(size_t)BC*OUTD]; // 91 MB
__device__ float g_mixin [BC*KTOT];       // [re(291) | im(291)] per bc
__device__ float g_mixout[BC*NOUT];       // [re(97) | im(97)] per bc
__device__ float g_yout  [BC*Hh];         // channel-major output before transpose
__device__ float g_V     [KTOT*NOUT];     // folded complex mix weight as real matrix

// ================= KT: 32x32 tiled transpose (B, R, C) -> (B, C, R) =================
__global__ void ktr(const float* __restrict__ in, float* __restrict__ outp, int R)
{
    __shared__ float tile[32][33];
    int b  = blockIdx.z;
    int c0 = blockIdx.x * 32, r0 = blockIdx.y * 32;
    int tx = threadIdx.x, ty = threadIdx.y;        // 32 x 8
    const float* ib = in   + (size_t)b * R * Cc;
    float*       ob = outp + (size_t)b * R * Cc;
#pragma unroll
    for (int y = 0; y < 32; y += 8) {
        int r = r0 + ty + y, c = c0 + tx;
        if (r < R && c < Cc) tile[ty + y][tx] = ib[(size_t)r * Cc + c];
    }
    __syncthreads();
#pragma unroll
    for (int y = 0; y < 32; y += 8) {
        int c = c0 + ty + y, r = r0 + tx;
        if (c < Cc && r < R) ob[(size_t)c * R + r] = tile[tx][ty + y];
    }
}

// ================= K1: normalize + classifier + softmaxes (coalesced inputs) ========
__global__ void __launch_bounds__(192) k1(
                   const float* __restrict__ r_in, const float* __restrict__ temp,
                   const float* __restrict__ cw, const float* __restrict__ bst,
                   const float* __restrict__ sb)
{
    int bc = blockIdx.x;
    int c = bc % Cc;
    __shared__ float xs[Ll];
    __shared__ float rb[64];
    __shared__ float lg[Ss];
    __shared__ float st2[2];
    int tid  = threadIdx.x;            // 192 threads
    int lane = tid & 31, wp = tid >> 5;

    float s0 = 0.f, s1 = 0.f;
    for (int l = tid; l < Ll; l += 192) {
        float v = g_xt[(size_t)bc*Ll + l];          // coalesced
        xs[l] = v; s0 += v; s1 += v*v;
    }
    for (int o = 16; o; o >>= 1) {
        s0 += __shfl_down_sync(0xffffffffu, s0, o);
        s1 += __shfl_down_sync(0xffffffffu, s1, o);
    }
    if (lane == 0) { rb[wp] = s0; rb[8+wp] = s1; }
    __syncthreads();
    if (tid == 0) {
        float a = 0.f, q = 0.f;
        for (int w = 0; w < 6; w++) { a += rb[w]; q += rb[8+w]; }
        float mu  = a * (1.f/Ll);
        float var = q * (1.f/Ll) - mu*mu;
        float sd  = sqrtf(var + 1e-8f);
        st2[0] = mu; st2[1] = sd;
        g_mu[bc] = mu; g_std[bc] = sd;
    }
    __syncthreads();
    float mu = st2[0], rs = 1.f / st2[1];
    for (int l = tid; l < Ll; l += 192)
        g_seq[bc*SEQ + l] = (xs[l] - mu) * rs;
    for (int h = tid; h < Hh; h += 192) {
        float v = g_yt[(size_t)bc*Hh + h];           // coalesced
        g_seq[bc*SEQ + Ll + h] = (v - mu) * rs;
    }

    // classifier logits: sum_l xt[l]*cw[s][l]  (raw xt!)
    float acc[Ss];
#pragma unroll
    for (int s = 0; s < Ss; s++) acc[s] = 0.f;
    for (int l = tid; l < Ll; l += 192) {
        float xv = xs[l];
#pragma unroll
        for (int s = 0; s < Ss; s++) acc[s] += xv * cw[s*Ll + l];
    }
#pragma unroll
    for (int s = 0; s < Ss; s++)
        for (int o = 16; o; o >>= 1)
            acc[s] += __shfl_down_sync(0xffffffffu, acc[s], o);
    __syncthreads();
    if (lane == 0) {
#pragma unroll
        for (int s = 0; s < Ss; s++) rb[wp*8 + s] = acc[s];
    }
    __syncthreads();
    if (tid < Ss) {
        float t = 0.f;
        for (int w = 0; w < 6; w++) t += rb[w*8 + tid];
        lg[tid] = t + sb[tid] + bst[c*Ss + tid];
    }
    __syncthreads();
    if (tid == 0) {
        float mx = lg[0];
        for (int s = 1; s < Ss; s++) mx = fmaxf(mx, lg[s]);
        float p[Ss], se = 0.f;
        for (int s = 0; s < Ss; s++) { p[s] = expf(lg[s] - mx); se += p[s]; }
        float inv = 1.f / se;
        for (int s = 0; s < Ss; s++) p[s] *= inv;

        float T = temp[0], iT = 1.f / T;
        float z[Kk+1], sg[Kk];
        z[0] = iT;
        float zm = z[0];
        for (int k = 0; k < Kk; k++) {
            float r = r_in[bc*Kk + k];
            sg[k] = (r > 0.f) ? 1.f : ((r < 0.f) ? -1.f : 0.f);
            z[k+1] = fabsf(r) * iT;
            zm = fmaxf(zm, z[k+1]);
        }
        float zs = 0.f, e[Kk+1];
        for (int i = 0; i <= Kk; i++) { e[i] = expf(z[i] - zm); zs += e[i]; }
        float izs = 1.f / zs;
        float cf[Kk];
        for (int k = 0; k < Kk; k++) cf[k] = e[k+1] * izs;

        float* co = &g_coeff[bc*KD];
        for (int s = 0; s < Ss; s++)
            for (int k = 0; k < Kk; k++) co[s*Kk + k] = p[s]*cf[k];
        for (int s = 0; s < Ss; s++) co[64 + s] = p[s];
        for (int k = 0; k < Kk; k++) g_sgn[bc*Kk + k] = sg[k];
    }
}

// ================= K0: build folded complex mix weight V[582][194] =================
__global__ void k0(const float* __restrict__ wr, const float* __restrict__ wi)
{
    int i = blockIdx.x * blockDim.x + threadIdx.x;
    if (i >= KTOT*NOUT) return;
    int f  = i / NOUT;
    int on = i % NOUT;
    int fr = (f < MIXF) ? f : f - MIXF;
    float v;
    if (on < FREQ) {                                  // real output rows
        v = (f < MIXF) ? wr[on*MIXF + fr] : -wi[on*MIXF + fr];
    } else {                                          // imag output rows
        int o = on - FREQ;
        v = (f < MIXF) ? wi[o*MIXF + fr] : wr[o*MIXF + fr];
    }
    g_V[i] = v;
}

// ================= K2: filt = coeff[72] @ W72[72,1649] =================
#define K2_TN 128
#define K2_TM 32
__global__ void __launch_bounds__(128) k2(
                   const float* __restrict__ mhw, const float* __restrict__ mhb)
{
    __shared__ float Wsh[KD*K2_TN];   // 36 KB
    __shared__ float Csh[KD*36];      // padded stride 36 for float4 + banks
    int tid = threadIdx.x;            // 128
    int o0 = blockIdx.x * K2_TN;
    int m0 = blockIdx.y * K2_TM;
    int o  = o0 + tid;

    for (int j = 0; j < KD; j++) {
        float v = 0.f;
        if (o < OUTD) {
            if (j < 64) v = mhw[(j >> 3)*(Kk*OUTD) + (j & 7)*OUTD + o];
            else        v = mhb[(j - 64)*OUTD + o];
        }
        Wsh[j*K2_TN + tid] = v;
    }
    for (int idx = tid; idx < K2_TM*KD; idx += 128) {
        int m = idx / KD, j = idx % KD;      // coalesced over j in g_coeff row
        Csh[j*36 + m] = g_coeff[(m0 + m)*KD + j];
    }
    __syncthreads();

    float accv[K2_TM];
#pragma unroll
    for (int m = 0; m < K2_TM; m++) accv[m] = 0.f;
    for (int j = 0; j < KD; j++) {
        float w = Wsh[j*K2_TN + tid];
        const float4* cp = (const float4*)(&Csh[j*36]);
#pragma unroll
        for (int mm = 0; mm < 8; mm++) {
            float4 cv = cp[mm];
            accv[4*mm+0] += cv.x * w;
            accv[4*mm+1] += cv.y * w;
            accv[4*mm+2] += cv.z * w;
            accv[4*mm+3] += cv.w * w;
        }
    }
    if (o < OUTD) {
#pragma unroll
        for (int m = 0; m < K2_TM; m++)
            g_filt[(size_t)(m0 + m)*OUTD + o] = accv[m];
    }
}

// ================= K3: gather + 9 DFTs (register-rotation twiddles) + mix_in =======
__global__ void __launch_bounds__(128) k3(
                   const int* __restrict__ lids, const int* __restrict__ shf)
{
    int bc = blockIdx.x;
    int b = bc / Cc;
    __shared__ float2 fadd[96][10];     // [h][t]: (x[h]+x[192-h], x[h]-x[192-h]); t-contig
    __shared__ float  x0s[9], x96s[9];
    __shared__ const float* srcp[9];
    __shared__ float  sgn9[12];
    __shared__ float  Xre[9][FREQ], Xim[9][FREQ];
    __shared__ float  flt[NF*FREQ];
    int tid = threadIdx.x;              // 128

    if (tid < 8) {
        int ld = lids[bc*Kk + tid];
        int sh = shf [bc*Kk + tid];
        srcp[tid] = &g_seq[(size_t)(b*Cc + ld)*SEQ + Ll - sh];
        sgn9[tid] = g_sgn[bc*Kk + tid];
    } else if (tid == 8) {
        srcp[8] = &g_seq[(size_t)bc*SEQ + Ll];
        sgn9[8] = 1.f;
    }
    for (int i = tid; i < NF*FREQ; i += 128) flt[i] = g_filt[(size_t)bc*OUTD + i];
    __syncthreads();

    // gather + fold directly from global (coalesced rows)
    for (int i = tid; i < 9*96; i += 128) {
        int t = i / 96, h = i - t*96;
        const float* src = srcp[t];
        float sg = sgn9[t];
        if (h == 0) { x0s[t] = src[0]*sg; x96s[t] = src[96]*sg; }
        else {
            float u = src[h]*sg, v = src[Hh - h]*sg;
            fadd[h][t] = make_float2(u + v, u - v);
        }
    }
    __syncthreads();

    // DFT: thread f computes all 9 transforms; twiddle via in-register rotation
    if (tid < FREQ) {
        int f = tid;
        float c, s;
        sincospif(f * (1.0f/96.0f), &s, &c);       // angle 2*pi*f/192
        float cr = c, ci = s;                      // value at h=1
        float ar0=0,ar1=0,ar2=0,ar3=0,ar4=0,ar5=0,ar6=0,ar7=0,ar8=0;
        float ai0=0,ai1=0,ai2=0,ai3=0,ai4=0,ai5=0,ai6=0,ai7=0,ai8=0;
#pragma unroll 5
        for (int h = 1; h <= 95; h++) {
            const float4* row = (const float4*)&fadd[h][0];   // broadcast loads
            float4 p01 = row[0];
            float4 p23 = row[1];
            float4 p45 = row[2];
            float4 p67 = row[3];
            float2 p8  = fadd[h][8];
            ar0 += p01.x*cr; ai0 += p01.y*ci;
            ar1 += p01.z*cr; ai1 += p01.w*ci;
            ar2 += p23.x*cr; ai2 += p23.y*ci;
            ar3 += p23.z*cr; ai3 += p23.w*ci;
            ar4 += p45.x*cr; ai4 += p45.y*ci;
            ar5 += p45.z*cr; ai5 += p45.w*ci;
            ar6 += p67.x*cr; ai6 += p67.y*ci;
            ar7 += p67.z*cr; ai7 += p67.w*ci;
            ar8 += p8.x *cr; ai8 += p8.y *ci;
            float nr = cr*c - ci*s;                 // rotate for next h
            ci = cr*s + ci*c;
            cr = nr;
        }
        float sgf = (f & 1) ? -1.f : 1.f;
        Xre[0][f] = x0s[0] + sgf*x96s[0] + ar0;  Xim[0][f] = -ai0;
        Xre[1][f] = x0s[1] + sgf*x96s[1] + ar1;  Xim[1][f] = -ai1;
        Xre[2][f] = x0s[2] + sgf*x96s[2] + ar2;  Xim[2][f] = -ai2;
        Xre[3][f] = x0s[3] + sgf*x96s[3] + ar3;  Xim[3][f] = -ai3;
        Xre[4][f] = x0s[4] + sgf*x96s[4] + ar4;  Xim[4][f] = -ai4;
        Xre[5][f] = x0s[5] + sgf*x96s[5] + ar5;  Xim[5][f] = -ai5;
        Xre[6][f] = x0s[6] + sgf*x96s[6] + ar6;  Xim[6][f] = -ai6;
        Xre[7][f] = x0s[7] + sgf*x96s[7] + ar7;  Xim[7][f] = -ai7;
        Xre[8][f] = x0s[8] + sgf*x96s[8] + ar8;  Xim[8][f] = -ai8;
    }
    __syncthreads();

    // mix_in = [lead_sum | diff_sum | self]  (re then im halves)
    for (int f = tid; f < FREQ; f += 128) {
        float yre = Xre[8][f], yim = Xim[8][f];
        float Are = 0.f, Aim = 0.f, Dre = 0.f, Dim = 0.f;
#pragma unroll
        for (int k = 0; k < Kk; k++) {
            float sre = Xre[k][f], sim = Xim[k][f];
            float fl = flt[k*FREQ + f];
            float fd = flt[(Kk + k)*FREQ + f];
            Are += sre*fl;          Aim += sim*fl;
            Dre += (sre - yre)*fd;  Dim += (sim - yim)*fd;
        }
        float fs = flt[2*Kk*FREQ + f];
        float* mo = &g_mixin[bc*KTOT];
        mo[f]                = Are;
        mo[FREQ + f]         = Dre;
        mo[2*FREQ + f]       = yre*fs;
        mo[MIXF + f]         = Aim;
        mo[MIXF + FREQ + f]  = Dim;
        mo[MIXF + 2*FREQ + f]= yim*fs;
    }
}

// ================= K4: mix_out = mix_in[582] @ V[582,194] + bias =================
#define K4_TN 128
#define K4_TM 32
#define K4_TK 32
__global__ void __launch_bounds__(128) k4(
                   const float* __restrict__ br, const float* __restrict__ bi)
{
    __shared__ float Vsh[K4_TK*K4_TN];   // 16 KB
    __shared__ float Ish[K4_TK*36];      // padded
    int tid = threadIdx.x;               // 128
    int n0 = blockIdx.x * K4_TN;
    int m0 = blockIdx.y * K4_TM;
    int on = n0 + tid;

    float accv[K4_TM];
#pragma unroll
    for (int m = 0; m < K4_TM; m++) accv[m] = 0.f;

    for (int kc = 0; kc < KTOT; kc += K4_TK) {
        __syncthreads();
        for (int kk = 0; kk < K4_TK; kk++) {
            int k = kc + kk;
            Vsh[kk*K4_TN + tid] = (k < KTOT && on < NOUT) ? g_V[k*NOUT + on] : 0.f;
        }
        for (int idx = tid; idx < K4_TM*K4_TK; idx += 128) {
            int m = idx / K4_TK, kk = idx % K4_TK;  // coalesced over kk
            int k = kc + kk;
            Ish[kk*36 + m] = (k < KTOT) ? g_mixin[(m0 + m)*KTOT + k] : 0.f;
        }
        __syncthreads();
        for (int kk = 0; kk < K4_TK; kk++) {
            float w = Vsh[kk*K4_TN + tid];
            const float4* ip = (const float4*)(&Ish[kk*36]);
#pragma unroll
            for (int mm = 0; mm < 8; mm++) {
                float4 iv = ip[mm];
                accv[4*mm+0] += iv.x * w;
                accv[4*mm+1] += iv.y * w;
                accv[4*mm+2] += iv.z * w;
                accv[4*mm+3] += iv.w * w;
            }
        }
    }
    if (on < NOUT) {
        float bias = (on < FREQ) ? br[on] : bi[on - FREQ];
#pragma unroll
        for (int m = 0; m < K4_TM; m++)
            g_mixout[(m0 + m)*NOUT + on] = accv[m] + bias;
    }
}

// ================= K5: irfft (register rotation) + denormalize, coalesced store ====
__global__ void __launch_bounds__(192) k5()
{
    int bc = blockIdx.x;
    __shared__ float2 mo[FREQ];
    int tid = threadIdx.x;               // 192
    for (int i = tid; i < FREQ; i += 192)
        mo[i] = make_float2(g_mixout[bc*NOUT + i], g_mixout[bc*NOUT + FREQ + i]);
    __syncthreads();

    int h = tid;                          // one output sample per thread
    float c, s;
    sincospif(h * (1.0f/96.0f), &s, &c);  // angle 2*pi*h/192
    float cr = c, ci = s;                 // value at f=1
    float acc = 0.f;
#pragma unroll 5
    for (int f = 1; f <= 95; f++) {
        float2 X = mo[f];                 // broadcast
        acc += X.x*cr - X.y*ci;           // Re(X * e^{+i theta})
        float nr = cr*c - ci*s;
        ci = cr*s + ci*c;
        cr = nr;
    }
    float R0 = mo[0].x, R96 = mo[96].x;   // imag of DC/Nyquist ignored (pocketfft c2r)
    float xh = (R0 + ((h & 1) ? -R96 : R96) + 2.f*acc) * (1.f/Hh);
    float yn = g_seq[bc*SEQ + Ll + h];
    g_yout[(size_t)bc*Hh + h] = (yn + xh) * g_std[bc] + g_mu[bc];  // coalesced
}

// ================= K6: transpose yout (B,C,H) -> out (B,H,C) =================
__global__ void k6(float* __restrict__ out)
{
    __shared__ float tile[32][33];
    int b  = blockIdx.z;
    int c0 = blockIdx.x * 32, h0 = blockIdx.y * 32;
    int tx = threadIdx.x, ty = threadIdx.y;        // 32 x 8
#pragma unroll
    for (int y = 0; y < 32; y += 8) {
        int c = c0 + ty + y;
        if (c < Cc) tile[ty + y][tx] = g_yout[((size_t)b*Cc + c)*Hh + h0 + tx];
    }
    __syncthreads();
#pragma unroll
    for (int y = 0; y < 32; y += 8) {
        int c = c0 + tx, h = h0 + ty + y;
        if (c < Cc) out[((size_t)b*Hh + h)*Cc + c] = tile[tx][ty + y];
    }
}

// ================= launcher =================
extern "C" void kernel_launch(void* const* d_in, const int* in_sizes, int n_in,
                              void* d_out, int out_size)
{
    const float* x   = (const float*)d_in[0];
    const float* yh  = (const float*)d_in[1];
    const float* r   = (const float*)d_in[2];
    const float* tmp = (const float*)d_in[3];
    const float* cw  = (const float*)d_in[4];
    const float* bst = (const float*)d_in[5];
    const float* sb  = (const float*)d_in[6];
    const float* mhw = (const float*)d_in[7];
    const float* mhb = (const float*)d_in[8];
    const float* mwr = (const float*)d_in[9];
    const float* mwi = (const float*)d_in[10];
    const float* mbr = (const float*)d_in[11];
    const float* mbi = (const float*)d_in[12];
    const int*   lid = (const int*)d_in[13];
    const int*   shf = (const int*)d_in[14];
    float* out = (float*)d_out;

    float* gxt; cudaGetSymbolAddress((void**)&gxt, g_xt);
    float* gyt; cudaGetSymbolAddress((void**)&gyt, g_yt);

    dim3 tb(32, 8);
    ktr<<<dim3((Cc+31)/32, (Ll+31)/32, Bb), tb>>>(x,  gxt, Ll);
    ktr<<<dim3((Cc+31)/32, (Hh+31)/32, Bb), tb>>>(yh, gyt, Hh);
    k1<<<BC, 192>>>(r, tmp, cw, bst, sb);
    k0<<<(KTOT*NOUT + 255)/256, 256>>>(mwr, mwi);
    k2<<<dim3((OUTD + K2_TN - 1)/K2_TN, BC/K2_TM), 128>>>(mhw, mhb);
    k3<<<BC, 128>>>(lid, shf);
    k4<<<dim3((NOUT + K4_TN - 1)/K4_TN, BC/K4_TM), 128>>>(mbr, mbi);
    k5<<<BC, 192>>>();
    k6<<<dim3((Cc+31)/32, Hh/32, Bb), tb>>>(out);
}

// round 10
// speedup vs baseline: 1.7060x; 1.0682x over previous
#include <cuda_runtime.h>
#include <math.h>

// ---------------- problem constants ----------------
#define Bb   16
#define Ll   336
#define Hh   192
#define Cc   862
#define Kk   8
#define Ss   8
#define FREQ 97            // H/2 + 1
#define NF   17            // 2K+1
#define OUTD 1649          // FREQ*NF
#define SEQ  528           // L+H
#define BC   (Bb*Cc)       // 13792
#define MIXF 291           // 3*FREQ
#define KD   72            // 64 (s,k) + 8 (s) rows
#define KTOT (2*MIXF)      // 582
#define NOUT (2*FREQ)      // 194

// ---------------- scratch (static device globals; no allocation) ----------------
__device__ float g_xt    [BC*Ll];         // transposed x  (B,C,L)
__device__ float g_yt    [BC*Hh];         // transposed y_hat (B,C,H)
__device__ float g_seq   [BC*SEQ];        // normalized [xn | yn] per channel
__device__ float g_mu    [BC];
__device__ float g_std   [BC];
__device__ float g_coeff [BC*KD];         // p[s]*cf[k] (64) then p[s] (8)
__device__ float g_sgn   [BC*Kk];
__device__ float g_filt  [(size_t)BC*OUTD]; // 91 MB
__device__ float g_mixin [BC*KTOT];       // [re(291) | im(291)] per bc
__device__ float g_mixout[BC*NOUT];       // [re(97) | im(97)] per bc
__device__ float g_yout  [BC*Hh];         // channel-major output before transpose
__device__ float g_V     [KTOT*NOUT];     // folded complex mix weight as real matrix

// ================= KT: 32x32 tiled transpose (B, R, C) -> (B, C, R) =================
__global__ void ktr(const float* __restrict__ in, float* __restrict__ outp, int R)
{
    __shared__ float tile[32][33];
    int b  = blockIdx.z;
    int c0 = blockIdx.x * 32, r0 = blockIdx.y * 32;
    int tx = threadIdx.x, ty = threadIdx.y;        // 32 x 8
    const float* ib = in   + (size_t)b * R * Cc;
    float*       ob = outp + (size_t)b * R * Cc;
#pragma unroll
    for (int y = 0; y < 32; y += 8) {
        int r = r0 + ty + y, c = c0 + tx;
        if (r < R && c < Cc) tile[ty + y][tx] = ib[(size_t)r * Cc + c];
    }
    __syncthreads();
#pragma unroll
    for (int y = 0; y < 32; y += 8) {
        int c = c0 + ty + y, r = r0 + tx;
        if (c < Cc && r < R) ob[(size_t)c * R + r] = tile[tx][ty + y];
    }
}

// ================= K1: normalize + classifier + softmaxes (coalesced inputs) ========
__global__ void __launch_bounds__(192) k1(
                   const float* __restrict__ r_in, const float* __restrict__ temp,
                   const float* __restrict__ cw, const float* __restrict__ bst,
                   const float* __restrict__ sb)
{
    int bc = blockIdx.x;
    int c = bc % Cc;
    __shared__ float xs[Ll];
    __shared__ float rb[64];
    __shared__ float lg[Ss];
    __shared__ float st2[2];
    int tid  = threadIdx.x;            // 192 threads
    int lane = tid & 31, wp = tid >> 5;

    float s0 = 0.f, s1 = 0.f;
    for (int l = tid; l < Ll; l += 192) {
        float v = g_xt[(size_t)bc*Ll + l];          // coalesced
        xs[l] = v; s0 += v; s1 += v*v;
    }
    for (int o = 16; o; o >>= 1) {
        s0 += __shfl_down_sync(0xffffffffu, s0, o);
        s1 += __shfl_down_sync(0xffffffffu, s1, o);
    }
    if (lane == 0) { rb[wp] = s0; rb[8+wp] = s1; }
    __syncthreads();
    if (tid == 0) {
        float a = 0.f, q = 0.f;
        for (int w = 0; w < 6; w++) { a += rb[w]; q += rb[8+w]; }
        float mu  = a * (1.f/Ll);
        float var = q * (1.f/Ll) - mu*mu;
        float sd  = sqrtf(var + 1e-8f);
        st2[0] = mu; st2[1] = sd;
        g_mu[bc] = mu; g_std[bc] = sd;
    }
    __syncthreads();
    float mu = st2[0], rs = 1.f / st2[1];
    for (int l = tid; l < Ll; l += 192)
        g_seq[bc*SEQ + l] = (xs[l] - mu) * rs;
    for (int h = tid; h < Hh; h += 192) {
        float v = g_yt[(size_t)bc*Hh + h];           // coalesced
        g_seq[bc*SEQ + Ll + h] = (v - mu) * rs;
    }

    // classifier logits: sum_l xt[l]*cw[s][l]  (raw xt!)
    float acc[Ss];
#pragma unroll
    for (int s = 0; s < Ss; s++) acc[s] = 0.f;
    for (int l = tid; l < Ll; l += 192) {
        float xv = xs[l];
#pragma unroll
        for (int s = 0; s < Ss; s++) acc[s] += xv * cw[s*Ll + l];
    }
#pragma unroll
    for (int s = 0; s < Ss; s++)
        for (int o = 16; o; o >>= 1)
            acc[s] += __shfl_down_sync(0xffffffffu, acc[s], o);
    __syncthreads();
    if (lane == 0) {
#pragma unroll
        for (int s = 0; s < Ss; s++) rb[wp*8 + s] = acc[s];
    }
    __syncthreads();
    if (tid < Ss) {
        float t = 0.f;
        for (int w = 0; w < 6; w++) t += rb[w*8 + tid];
        lg[tid] = t + sb[tid] + bst[c*Ss + tid];
    }
    __syncthreads();
    if (tid == 0) {
        float mx = lg[0];
        for (int s = 1; s < Ss; s++) mx = fmaxf(mx, lg[s]);
        float p[Ss], se = 0.f;
        for (int s = 0; s < Ss; s++) { p[s] = expf(lg[s] - mx); se += p[s]; }
        float inv = 1.f / se;
        for (int s = 0; s < Ss; s++) p[s] *= inv;

        float T = temp[0], iT = 1.f / T;
        float z[Kk+1], sg[Kk];
        z[0] = iT;
        float zm = z[0];
        for (int k = 0; k < Kk; k++) {
            float r = r_in[bc*Kk + k];
            sg[k] = (r > 0.f) ? 1.f : ((r < 0.f) ? -1.f : 0.f);
            z[k+1] = fabsf(r) * iT;
            zm = fmaxf(zm, z[k+1]);
        }
        float zs = 0.f, e[Kk+1];
        for (int i = 0; i <= Kk; i++) { e[i] = expf(z[i] - zm); zs += e[i]; }
        float izs = 1.f / zs;
        float cf[Kk];
        for (int k = 0; k < Kk; k++) cf[k] = e[k+1] * izs;

        float* co = &g_coeff[bc*KD];
        for (int s = 0; s < Ss; s++)
            for (int k = 0; k < Kk; k++) co[s*Kk + k] = p[s]*cf[k];
        for (int s = 0; s < Ss; s++) co[64 + s] = p[s];
        for (int k = 0; k < Kk; k++) g_sgn[bc*Kk + k] = sg[k];
    }
}

// ================= K0: build folded complex mix weight V[582][194] =================
__global__ void k0(const float* __restrict__ wr, const float* __restrict__ wi)
{
    int i = blockIdx.x * blockDim.x + threadIdx.x;
    if (i >= KTOT*NOUT) return;
    int f  = i / NOUT;
    int on = i % NOUT;
    int fr = (f < MIXF) ? f : f - MIXF;
    float v;
    if (on < FREQ) {                                  // real output rows
        v = (f < MIXF) ? wr[on*MIXF + fr] : -wi[on*MIXF + fr];
    } else {                                          // imag output rows
        int o = on - FREQ;
        v = (f < MIXF) ? wi[o*MIXF + fr] : wr[o*MIXF + fr];
    }
    g_V[i] = v;
}

// ================= K2: filt = coeff[72] @ W72[72,1649] =================
#define K2_TN 128
#define K2_TM 32
__global__ void __launch_bounds__(128) k2(
                   const float* __restrict__ mhw, const float* __restrict__ mhb)
{
    __shared__ float Wsh[KD*K2_TN];   // 36 KB
    __shared__ float Csh[KD*36];      // padded stride 36 for float4 + banks
    int tid = threadIdx.x;            // 128
    int o0 = blockIdx.x * K2_TN;
    int m0 = blockIdx.y * K2_TM;
    int o  = o0 + tid;

    for (int j = 0; j < KD; j++) {
        float v = 0.f;
        if (o < OUTD) {
            if (j < 64) v = mhw[(j >> 3)*(Kk*OUTD) + (j & 7)*OUTD + o];
            else        v = mhb[(j - 64)*OUTD + o];
        }
        Wsh[j*K2_TN + tid] = v;
    }
    for (int idx = tid; idx < K2_TM*KD; idx += 128) {
        int m = idx / KD, j = idx % KD;      // coalesced over j in g_coeff row
        Csh[j*36 + m] = g_coeff[(m0 + m)*KD + j];
    }
    __syncthreads();

    float accv[K2_TM];
#pragma unroll
    for (int m = 0; m < K2_TM; m++) accv[m] = 0.f;
    for (int j = 0; j < KD; j++) {
        float w = Wsh[j*K2_TN + tid];
        const float4* cp = (const float4*)(&Csh[j*36]);
#pragma unroll
        for (int mm = 0; mm < 8; mm++) {
            float4 cv = cp[mm];
            accv[4*mm+0] += cv.x * w;
            accv[4*mm+1] += cv.y * w;
            accv[4*mm+2] += cv.z * w;
            accv[4*mm+3] += cv.w * w;
        }
    }
    if (o < OUTD) {
#pragma unroll
        for (int m = 0; m < K2_TM; m++)
            g_filt[(size_t)(m0 + m)*OUTD + o] = accv[m];
    }
}

// ================= K3: gather + 9 DFTs (double fold, 47-iter) + mix_in =============
__global__ void __launch_bounds__(128) k3(
                   const int* __restrict__ lids, const int* __restrict__ shf)
{
    int bc = blockIdx.x;
    int b = bc / Cc;
    __shared__ float2 fadd[97][10];     // [h][t]: (A=x[h]+x[192-h], B=x[h]-x[192-h]); h=1..96 slots, use 1..95
    __shared__ float  comb[48][2][24];  // [h=1..47][parity of f][A'0..8 pad..11, B'0..8 @12..20]
    __shared__ float  x0s[9], x96s[9];
    __shared__ const float* srcp[9];
    __shared__ float  sgn9[12];
    __shared__ float  Xre[9][FREQ], Xim[9][FREQ];
    __shared__ float  flt[NF*FREQ];
    int tid = threadIdx.x;              // 128

    if (tid < 8) {
        int ld = lids[bc*Kk + tid];
        int sh = shf [bc*Kk + tid];
        srcp[tid] = &g_seq[(size_t)(b*Cc + ld)*SEQ + Ll - sh];
        sgn9[tid] = g_sgn[bc*Kk + tid];
    } else if (tid == 8) {
        srcp[8] = &g_seq[(size_t)bc*SEQ + Ll];
        sgn9[8] = 1.f;
    }
    for (int i = tid; i < NF*FREQ; i += 128) flt[i] = g_filt[(size_t)bc*OUTD + i];
    __syncthreads();

    // gather + first fold directly from global (coalesced rows)
    for (int i = tid; i < 9*96; i += 128) {
        int t = i / 96, h = i - t*96;
        const float* src = srcp[t];
        float sg = sgn9[t];
        if (h == 0) { x0s[t] = src[0]*sg; x96s[t] = src[96]*sg; }
        else {
            float u = src[h]*sg, v = src[Hh - h]*sg;
            fadd[h][t] = make_float2(u + v, u - v);
        }
    }
    __syncthreads();

    // second fold: pair (h, 96-h), h=1..47, split by parity of f
    // even f: cos pair = A_h + A_{96-h};  sin pair = B_h - B_{96-h}
    // odd  f: cos pair = A_h - A_{96-h};  sin pair = B_h + B_{96-h}
    for (int i = tid; i < 9*47; i += 128) {
        int t = i / 47, h = i - t*47 + 1;
        float2 p1 = fadd[h][t], p2 = fadd[96 - h][t];
        comb[h][0][t]      = p1.x + p2.x;
        comb[h][0][12 + t] = p1.y - p2.y;
        comb[h][1][t]      = p1.x - p2.x;
        comb[h][1][12 + t] = p1.y + p2.y;
    }
    __syncthreads();

    // DFT: thread f computes all 9 transforms over 47 folded terms
    if (tid < FREQ) {
        int f = tid;
        int par = f & 1;
        float c, s;
        sincospif(f * (1.0f/96.0f), &s, &c);       // angle 2*pi*f/192
        float cr = c, ci = s;                      // value at h=1
        float ar0=0,ar1=0,ar2=0,ar3=0,ar4=0,ar5=0,ar6=0,ar7=0,ar8=0;
        float ai0=0,ai1=0,ai2=0,ai3=0,ai4=0,ai5=0,ai6=0,ai7=0,ai8=0;
#pragma unroll 47
        for (int h = 1; h <= 47; h++) {
            const float* pc = &comb[h][par][0];
            const float4* ap = (const float4*)pc;
            float4 a03 = ap[0];
            float4 a47 = ap[1];
            float  a8  = pc[8];
            const float4* bp = (const float4*)(pc + 12);
            float4 b03 = bp[0];
            float4 b47 = bp[1];
            float  b8  = pc[20];
            ar0 += a03.x*cr; ai0 += b03.x*ci;
            ar1 += a03.y*cr; ai1 += b03.y*ci;
            ar2 += a03.z*cr; ai2 += b03.z*ci;
            ar3 += a03.w*cr; ai3 += b03.w*ci;
            ar4 += a47.x*cr; ai4 += b47.x*ci;
            ar5 += a47.y*cr; ai5 += b47.y*ci;
            ar6 += a47.z*cr; ai6 += b47.z*ci;
            ar7 += a47.w*cr; ai7 += b47.w*ci;
            ar8 += a8 *cr;   ai8 += b8 *ci;
            float nr = cr*c - ci*s;                 // rotate for next h
            ci = cr*s + ci*c;
            cr = nr;
        }
        // h = 48 term: cos(pi f/2), sin(pi f/2) in {0, +-1}
        {
            const float2* r48 = &fadd[48][0];
            if (par == 0) {
                float cc = ((f & 3) == 0) ? 1.f : -1.f;
                ar0 += r48[0].x*cc; ar1 += r48[1].x*cc; ar2 += r48[2].x*cc;
                ar3 += r48[3].x*cc; ar4 += r48[4].x*cc; ar5 += r48[5].x*cc;
                ar6 += r48[6].x*cc; ar7 += r48[7].x*cc; ar8 += r48[8].x*cc;
            } else {
                float ss = ((f & 3) == 1) ? 1.f : -1.f;
                ai0 += r48[0].y*ss; ai1 += r48[1].y*ss; ai2 += r48[2].y*ss;
                ai3 += r48[3].y*ss; ai4 += r48[4].y*ss; ai5 += r48[5].y*ss;
                ai6 += r48[6].y*ss; ai7 += r48[7].y*ss; ai8 += r48[8].y*ss;
            }
        }
        float sgf = (par == 0) ? 1.f : -1.f;       // (-1)^f
        Xre[0][f] = x0s[0] + sgf*x96s[0] + ar0;  Xim[0][f] = -ai0;
        Xre[1][f] = x0s[1] + sgf*x96s[1] + ar1;  Xim[1][f] = -ai1;
        Xre[2][f] = x0s[2] + sgf*x96s[2] + ar2;  Xim[2][f] = -ai2;
        Xre[3][f] = x0s[3] + sgf*x96s[3] + ar3;  Xim[3][f] = -ai3;
        Xre[4][f] = x0s[4] + sgf*x96s[4] + ar4;  Xim[4][f] = -ai4;
        Xre[5][f] = x0s[5] + sgf*x96s[5] + ar5;  Xim[5][f] = -ai5;
        Xre[6][f] = x0s[6] + sgf*x96s[6] + ar6;  Xim[6][f] = -ai6;
        Xre[7][f] = x0s[7] + sgf*x96s[7] + ar7;  Xim[7][f] = -ai7;
        Xre[8][f] = x0s[8] + sgf*x96s[8] + ar8;  Xim[8][f] = -ai8;
    }
    __syncthreads();

    // mix_in = [lead_sum | diff_sum | self]  (re then im halves)
    for (int f = tid; f < FREQ; f += 128) {
        float yre = Xre[8][f], yim = Xim[8][f];
        float Are = 0.f, Aim = 0.f, Dre = 0.f, Dim = 0.f;
#pragma unroll
        for (int k = 0; k < Kk; k++) {
            float sre = Xre[k][f], sim = Xim[k][f];
            float fl = flt[k*FREQ + f];
            float fd = flt[(Kk + k)*FREQ + f];
            Are += sre*fl;          Aim += sim*fl;
            Dre += (sre - yre)*fd;  Dim += (sim - yim)*fd;
        }
        float fs = flt[2*Kk*FREQ + f];
        float* mo = &g_mixin[bc*KTOT];
        mo[f]                = Are;
        mo[FREQ + f]         = Dre;
        mo[2*FREQ + f]       = yre*fs;
        mo[MIXF + f]         = Aim;
        mo[MIXF + FREQ + f]  = Dim;
        mo[MIXF + 2*FREQ + f]= yim*fs;
    }
}

// ================= K4: mix_out = mix_in[582] @ V[582,194] + bias =================
#define K4_TN 128
#define K4_TM 32
#define K4_TK 32
__global__ void __launch_bounds__(128) k4(
                   const float* __restrict__ br, const float* __restrict__ bi)
{
    __shared__ float Vsh[K4_TK*K4_TN];   // 16 KB
    __shared__ float Ish[K4_TK*36];      // padded
    int tid = threadIdx.x;               // 128
    int n0 = blockIdx.x * K4_TN;
    int m0 = blockIdx.y * K4_TM;
    int on = n0 + tid;

    float accv[K4_TM];
#pragma unroll
    for (int m = 0; m < K4_TM; m++) accv[m] = 0.f;

    for (int kc = 0; kc < KTOT; kc += K4_TK) {
        __syncthreads();
        for (int kk = 0; kk < K4_TK; kk++) {
            int k = kc + kk;
            Vsh[kk*K4_TN + tid] = (k < KTOT && on < NOUT) ? g_V[k*NOUT + on] : 0.f;
        }
        for (int idx = tid; idx < K4_TM*K4_TK; idx += 128) {
            int m = idx / K4_TK, kk = idx % K4_TK;  // coalesced over kk
            int k = kc + kk;
            Ish[kk*36 + m] = (k < KTOT) ? g_mixin[(m0 + m)*KTOT + k] : 0.f;
        }
        __syncthreads();
        for (int kk = 0; kk < K4_TK; kk++) {
            float w = Vsh[kk*K4_TN + tid];
            const float4* ip = (const float4*)(&Ish[kk*36]);
#pragma unroll
            for (int mm = 0; mm < 8; mm++) {
                float4 iv = ip[mm];
                accv[4*mm+0] += iv.x * w;
                accv[4*mm+1] += iv.y * w;
                accv[4*mm+2] += iv.z * w;
                accv[4*mm+3] += iv.w * w;
            }
        }
    }
    if (on < NOUT) {
        float bias = (on < FREQ) ? br[on] : bi[on - FREQ];
#pragma unroll
        for (int m = 0; m < K4_TM; m++)
            g_mixout[(m0 + m)*NOUT + on] = accv[m] + bias;
    }
}

// ================= K5: irfft (double fold, 47-iter) + denormalize =================
__global__ void __launch_bounds__(192) k5()
{
    int bc = blockIdx.x;
    __shared__ float2 mo[FREQ];
    __shared__ float2 cb5[48][2];        // [f=1..47][parity of h]: (C, D)
    int tid = threadIdx.x;               // 192
    for (int i = tid; i < FREQ; i += 192)
        mo[i] = make_float2(g_mixout[bc*NOUT + i], g_mixout[bc*NOUT + FREQ + i]);
    __syncthreads();
    // pair (f, 96-f), f=1..47:
    // even h: C = Xr_f + Xr_{96-f};  D = -Xi_f + Xi_{96-f}
    // odd  h: C = Xr_f - Xr_{96-f};  D = -Xi_f - Xi_{96-f}
    for (int f = tid + 1; f <= 47; f += 192) {
        float2 X1 = mo[f], X2 = mo[96 - f];
        cb5[f][0] = make_float2(X1.x + X2.x, -X1.y + X2.y);
        cb5[f][1] = make_float2(X1.x - X2.x, -X1.y - X2.y);
    }
    __syncthreads();

    int h = tid;                          // one output sample per thread
    int par = h & 1;
    float c, s;
    sincospif(h * (1.0f/96.0f), &s, &c);  // angle 2*pi*h/192
    float cr = c, ci = s;                 // value at f=1
    float acc = 0.f;
#pragma unroll 47
    for (int f = 1; f <= 47; f++) {
        float2 CD = cb5[f][par];
        acc += CD.x*cr + CD.y*ci;         // C cos + D sin
        float nr = cr*c - ci*s;
        ci = cr*s + ci*c;
        cr = nr;
    }
    // f = 48 term: Xr48*cos(pi h/2) - Xi48*sin(pi h/2)
    {
        float2 X48 = mo[48];
        if (par == 0) acc += X48.x * (((h & 3) == 0) ? 1.f : -1.f);
        else          acc -= X48.y * (((h & 3) == 1) ? 1.f : -1.f);
    }
    float R0 = mo[0].x, R96 = mo[96].x;   // imag of DC/Nyquist ignored (pocketfft c2r)
    float xh = (R0 + ((par == 0) ? R96 : -R96) + 2.f*acc) * (1.f/Hh);
    float yn = g_seq[bc*SEQ + Ll + h];
    g_yout[(size_t)bc*Hh + h] = (yn + xh) * g_std[bc] + g_mu[bc];  // coalesced
}

// ================= K6: transpose yout (B,C,H) -> out (B,H,C) =================
__global__ void k6(float* __restrict__ out)
{
    __shared__ float tile[32][33];
    int b  = blockIdx.z;
    int c0 = blockIdx.x * 32, h0 = blockIdx.y * 32;
    int tx = threadIdx.x, ty = threadIdx.y;        // 32 x 8
#pragma unroll
    for (int y = 0; y < 32; y += 8) {
        int c = c0 + ty + y;
        if (c < Cc) tile[ty + y][tx] = g_yout[((size_t)b*Cc + c)*Hh + h0 + tx];
    }
    __syncthreads();
#pragma unroll
    for (int y = 0; y < 32; y += 8) {
        int c = c0 + tx, h = h0 + ty + y;
        if (c < Cc) out[((size_t)b*Hh + h)*Cc + c] = tile[tx][ty + y];
    }
}

// ================= launcher =================
extern "C" void kernel_launch(void* const* d_in, const int* in_sizes, int n_in,
                              void* d_out, int out_size)
{
    const float* x   = (const float*)d_in[0];
    const float* yh  = (const float*)d_in[1];
    const float* r   = (const float*)d_in[2];
    const float* tmp = (const float*)d_in[3];
    const float* cw  = (const float*)d_in[4];
    const float* bst = (const float*)d_in[5];
    const float* sb  = (const float*)d_in[6];
    const float* mhw = (const float*)d_in[7];
    const float* mhb = (const float*)d_in[8];
    const float* mwr = (const float*)d_in[9];
    const float* mwi = (const float*)d_in[10];
    const float* mbr = (const float*)d_in[11];
    const float* mbi = (const float*)d_in[12];
    const int*   lid = (const int*)d_in[13];
    const int*   shf = (const int*)d_in[14];
    float* out = (float*)d_out;

    float* gxt; cudaGetSymbolAddress((void**)&gxt, g_xt);
    float* gyt; cudaGetSymbolAddress((void**)&gyt, g_yt);

    dim3 tb(32, 8);
    ktr<<<dim3((Cc+31)/32, (Ll+31)/32, Bb), tb>>>(x,  gxt, Ll);
    ktr<<<dim3((Cc+31)/32, (Hh+31)/32, Bb), tb>>>(yh, gyt, Hh);
    k1<<<BC, 192>>>(r, tmp, cw, bst, sb);
    k0<<<(KTOT*NOUT + 255)/256, 256>>>(mwr, mwi);
    k2<<<dim3((OUTD + K2_TN - 1)/K2_TN, BC/K2_TM), 128>>>(mhw, mhb);
    k3<<<BC, 128>>>(lid, shf);
    k4<<<dim3((NOUT + K4_TN - 1)/K4_TN, BC/K4_TM), 128>>>(mbr, mbi);
    k5<<<BC, 192>>>();
    k6<<<dim3((Cc+31)/32, Hh/32, Bb), tb>>>(out);
}

// round 12
// speedup vs baseline: 1.7718x; 1.0386x over previous
#include <cuda_runtime.h>
#include <math.h>

// ---------------- problem constants ----------------
#define Bb   16
#define Ll   336
#define Hh   192
#define Cc   862
#define Kk   8
#define Ss   8
#define FREQ 97            // H/2 + 1
#define NF   17            // 2K+1
#define OUTD 1649          // FREQ*NF
#define SEQ  528           // L+H
#define BC   (Bb*Cc)       // 13792
#define MIXF 291           // 3*FREQ
#define KD   72            // 64 (s,k) + 8 (s) rows
#define KTOT (2*MIXF)      // 582
#define NOUT (2*FREQ)      // 194

// ---------------- scratch (static device globals; no allocation) ----------------
__device__ float g_xt    [BC*Ll];         // transposed x  (B,C,L)
__device__ float g_yt    [BC*Hh];         // transposed y_hat (B,C,H)
__device__ float g_seq   [BC*SEQ];        // normalized [xn | yn] per channel
__device__ float g_mu    [BC];
__device__ float g_std   [BC];
__device__ float g_coeff [BC*KD];         // p[s]*cf[k] (64) then p[s] (8)
__device__ float g_sgn   [BC*Kk];
__device__ float g_filt  [(size_t)BC*OUTD]; // 91 MB
__device__ float g_mixin [BC*KTOT];       // [re(291) | im(291)] per bc
__device__ float g_mixout[BC*NOUT];       // [re(97) | im(97)] per bc
__device__ float g_yout  [BC*Hh];         // channel-major output before transpose
__device__ float g_V     [KTOT*NOUT];     // folded complex mix weight as real matrix

// ================= KT: 32x32 tiled transpose (B, R, C) -> (B, C, R) =================
__global__ void ktr(const float* __restrict__ in, float* __restrict__ outp, int R)
{
    __shared__ float tile[32][33];
    int b  = blockIdx.z;
    int c0 = blockIdx.x * 32, r0 = blockIdx.y * 32;
    int tx = threadIdx.x, ty = threadIdx.y;        // 32 x 8
    const float* ib = in   + (size_t)b * R * Cc;
    float*       ob = outp + (size_t)b * R * Cc;
#pragma unroll
    for (int y = 0; y < 32; y += 8) {
        int r = r0 + ty + y, c = c0 + tx;
        if (r < R && c < Cc) tile[ty + y][tx] = ib[(size_t)r * Cc + c];
    }
    __syncthreads();
#pragma unroll
    for (int y = 0; y < 32; y += 8) {
        int c = c0 + ty + y, r = r0 + tx;
        if (c < Cc && r < R) ob[(size_t)c * R + r] = tile[tx][ty + y];
    }
}

// ================= K1: normalize + classifier + softmaxes (coalesced inputs) ========
__global__ void __launch_bounds__(192) k1(
                   const float* __restrict__ r_in, const float* __restrict__ temp,
                   const float* __restrict__ cw, const float* __restrict__ bst,
                   const float* __restrict__ sb)
{
    int bc = blockIdx.x;
    int c = bc % Cc;
    __shared__ float xs[Ll];
    __shared__ float rb[64];
    __shared__ float lg[Ss];
    __shared__ float st2[2];
    int tid  = threadIdx.x;            // 192 threads
    int lane = tid & 31, wp = tid >> 5;

    float s0 = 0.f, s1 = 0.f;
    for (int l = tid; l < Ll; l += 192) {
        float v = g_xt[(size_t)bc*Ll + l];          // coalesced
        xs[l] = v; s0 += v; s1 += v*v;
    }
    for (int o = 16; o; o >>= 1) {
        s0 += __shfl_down_sync(0xffffffffu, s0, o);
        s1 += __shfl_down_sync(0xffffffffu, s1, o);
    }
    if (lane == 0) { rb[wp] = s0; rb[8+wp] = s1; }
    __syncthreads();
    if (tid == 0) {
        float a = 0.f, q = 0.f;
        for (int w = 0; w < 6; w++) { a += rb[w]; q += rb[8+w]; }
        float mu  = a * (1.f/Ll);
        float var = q * (1.f/Ll) - mu*mu;
        float sd  = sqrtf(var + 1e-8f);
        st2[0] = mu; st2[1] = sd;
        g_mu[bc] = mu; g_std[bc] = sd;
    }
    __syncthreads();
    float mu = st2[0], rs = 1.f / st2[1];
    for (int l = tid; l < Ll; l += 192)
        g_seq[bc*SEQ + l] = (xs[l] - mu) * rs;
    for (int h = tid; h < Hh; h += 192) {
        float v = g_yt[(size_t)bc*Hh + h];           // coalesced
        g_seq[bc*SEQ + Ll + h] = (v - mu) * rs;
    }

    // classifier logits: sum_l xt[l]*cw[s][l]  (raw xt!)
    float acc[Ss];
#pragma unroll
    for (int s = 0; s < Ss; s++) acc[s] = 0.f;
    for (int l = tid; l < Ll; l += 192) {
        float xv = xs[l];
#pragma unroll
        for (int s = 0; s < Ss; s++) acc[s] += xv * cw[s*Ll + l];
    }
#pragma unroll
    for (int s = 0; s < Ss; s++)
        for (int o = 16; o; o >>= 1)
            acc[s] += __shfl_down_sync(0xffffffffu, acc[s], o);
    __syncthreads();
    if (lane == 0) {
#pragma unroll
        for (int s = 0; s < Ss; s++) rb[wp*8 + s] = acc[s];
    }
    __syncthreads();
    if (tid < Ss) {
        float t = 0.f;
        for (int w = 0; w < 6; w++) t += rb[w*8 + tid];
        lg[tid] = t + sb[tid] + bst[c*Ss + tid];
    }
    __syncthreads();
    if (tid == 0) {
        float mx = lg[0];
        for (int s = 1; s < Ss; s++) mx = fmaxf(mx, lg[s]);
        float p[Ss], se = 0.f;
        for (int s = 0; s < Ss; s++) { p[s] = expf(lg[s] - mx); se += p[s]; }
        float inv = 1.f / se;
        for (int s = 0; s < Ss; s++) p[s] *= inv;

        float T = temp[0], iT = 1.f / T;
        float z[Kk+1], sg[Kk];
        z[0] = iT;
        float zm = z[0];
        for (int k = 0; k < Kk; k++) {
            float r = r_in[bc*Kk + k];
            sg[k] = (r > 0.f) ? 1.f : ((r < 0.f) ? -1.f : 0.f);
            z[k+1] = fabsf(r) * iT;
            zm = fmaxf(zm, z[k+1]);
        }
        float zs = 0.f, e[Kk+1];
        for (int i = 0; i <= Kk; i++) { e[i] = expf(z[i] - zm); zs += e[i]; }
        float izs = 1.f / zs;
        float cf[Kk];
        for (int k = 0; k < Kk; k++) cf[k] = e[k+1] * izs;

        float* co = &g_coeff[bc*KD];
        for (int s = 0; s < Ss; s++)
            for (int k = 0; k < Kk; k++) co[s*Kk + k] = p[s]*cf[k];
        for (int s = 0; s < Ss; s++) co[64 + s] = p[s];
        for (int k = 0; k < Kk; k++) g_sgn[bc*Kk + k] = sg[k];
    }
}

// ================= K0: build folded complex mix weight V[582][194] =================
__global__ void k0(const float* __restrict__ wr, const float* __restrict__ wi)
{
    int i = blockIdx.x * blockDim.x + threadIdx.x;
    if (i >= KTOT*NOUT) return;
    int f  = i / NOUT;
    int on = i % NOUT;
    int fr = (f < MIXF) ? f : f - MIXF;
    float v;
    if (on < FREQ) {                                  // real output rows
        v = (f < MIXF) ? wr[on*MIXF + fr] : -wi[on*MIXF + fr];
    } else {                                          // imag output rows
        int o = on - FREQ;
        v = (f < MIXF) ? wi[o*MIXF + fr] : wr[o*MIXF + fr];
    }
    g_V[i] = v;
}

// ================= K2: filt = coeff[72] @ W72[72,1649]  (W streamed from L2) =======
#define K2_TN 128
#define K2_TM 32
__global__ void __launch_bounds__(128) k2(
                   const float* __restrict__ mhw, const float* __restrict__ mhb)
{
    __shared__ float Csh[KD*36];      // padded stride 36 for float4 + banks
    int tid = threadIdx.x;            // 128
    int o0 = blockIdx.x * K2_TN;
    int m0 = blockIdx.y * K2_TM;
    int o  = o0 + tid;
    bool valid = (o < OUTD);
    int  oc = valid ? o : (OUTD - 1);  // clamp: keeps loads in-bounds, result discarded

    for (int idx = tid; idx < K2_TM*KD; idx += 128) {
        int m = idx / KD, j = idx % KD;      // coalesced over j in g_coeff row
        Csh[j*36 + m] = g_coeff[(m0 + m)*KD + j];
    }
    __syncthreads();

    float accv[K2_TM];
#pragma unroll
    for (int m = 0; m < K2_TM; m++) accv[m] = 0.f;

    // note: (j>>3)*(Kk*OUTD) + (j&7)*OUTD == j*OUTD  -> W rows are simply mhw[j*OUTD + o]
    const float* wp = mhw + oc;
#pragma unroll 8
    for (int j = 0; j < 64; j++) {
        float w = __ldg(&wp[(size_t)j*OUTD]);        // coalesced, L2-resident
        const float4* cp = (const float4*)(&Csh[j*36]);
#pragma unroll
        for (int mm = 0; mm < 8; mm++) {
            float4 cv = cp[mm];
            accv[4*mm+0] += cv.x * w;
            accv[4*mm+1] += cv.y * w;
            accv[4*mm+2] += cv.z * w;
            accv[4*mm+3] += cv.w * w;
        }
    }
    const float* bp = mhb + oc;
#pragma unroll
    for (int j = 0; j < 8; j++) {
        float w = __ldg(&bp[(size_t)j*OUTD]);
        const float4* cp = (const float4*)(&Csh[(64 + j)*36]);
#pragma unroll
        for (int mm = 0; mm < 8; mm++) {
            float4 cv = cp[mm];
            accv[4*mm+0] += cv.x * w;
            accv[4*mm+1] += cv.y * w;
            accv[4*mm+2] += cv.z * w;
            accv[4*mm+3] += cv.w * w;
        }
    }
    if (valid) {
#pragma unroll
        for (int m = 0; m < K2_TM; m++)
            g_filt[(size_t)(m0 + m)*OUTD + o] = accv[m];
    }
}

// ================= K3: gather + 9 DFTs (double fold, 47-iter) + mix_in =============
__global__ void __launch_bounds__(128) k3(
                   const int* __restrict__ lids, const int* __restrict__ shf)
{
    int bc = blockIdx.x;
    int b = bc / Cc;
    __shared__ float2 fadd[97][10];     // [h][t]: (A=x[h]+x[192-h], B=x[h]-x[192-h]); h=1..96 slots, use 1..95
    __shared__ float  comb[48][2][24];  // [h=1..47][parity of f][A'0..8 pad..11, B'0..8 @12..20]
    __shared__ float  x0s[9], x96s[9];
    __shared__ const float* srcp[9];
    __shared__ float  sgn9[12];
    __shared__ float  Xre[9][FREQ], Xim[9][FREQ];
    __shared__ float  flt[NF*FREQ];
    int tid = threadIdx.x;              // 128

    if (tid < 8) {
        int ld = lids[bc*Kk + tid];
        int sh = shf [bc*Kk + tid];
        srcp[tid] = &g_seq[(size_t)(b*Cc + ld)*SEQ + Ll - sh];
        sgn9[tid] = g_sgn[bc*Kk + tid];
    } else if (tid == 8) {
        srcp[8] = &g_seq[(size_t)bc*SEQ + Ll];
        sgn9[8] = 1.f;
    }
    for (int i = tid; i < NF*FREQ; i += 128) flt[i] = g_filt[(size_t)bc*OUTD + i];
    __syncthreads();

    // gather + first fold directly from global (coalesced rows)
    for (int i = tid; i < 9*96; i += 128) {
        int t = i / 96, h = i - t*96;
        const float* src = srcp[t];
        float sg = sgn9[t];
        if (h == 0) { x0s[t] = src[0]*sg; x96s[t] = src[96]*sg; }
        else {
            float u = src[h]*sg, v = src[Hh - h]*sg;
            fadd[h][t] = make_float2(u + v, u - v);
        }
    }
    __syncthreads();

    // second fold: pair (h, 96-h), h=1..47, split by parity of f
    for (int i = tid; i < 9*47; i += 128) {
        int t = i / 47, h = i - t*47 + 1;
        float2 p1 = fadd[h][t], p2 = fadd[96 - h][t];
        comb[h][0][t]      = p1.x + p2.x;
        comb[h][0][12 + t] = p1.y - p2.y;
        comb[h][1][t]      = p1.x - p2.x;
        comb[h][1][12 + t] = p1.y + p2.y;
    }
    __syncthreads();

    // DFT: thread f computes all 9 transforms over 47 folded terms
    if (tid < FREQ) {
        int f = tid;
        int par = f & 1;
        float c, s;
        sincospif(f * (1.0f/96.0f), &s, &c);       // angle 2*pi*f/192
        float cr = c, ci = s;                      // value at h=1
        float ar0=0,ar1=0,ar2=0,ar3=0,ar4=0,ar5=0,ar6=0,ar7=0,ar8=0;
        float ai0=0,ai1=0,ai2=0,ai3=0,ai4=0,ai5=0,ai6=0,ai7=0,ai8=0;
#pragma unroll 47
        for (int h = 1; h <= 47; h++) {
            const float* pc = &comb[h][par][0];
            const float4* ap = (const float4*)pc;
            float4 a03 = ap[0];
            float4 a47 = ap[1];
            float  a8  = pc[8];
            const float4* bp = (const float4*)(pc + 12);
            float4 b03 = bp[0];
            float4 b47 = bp[1];
            float  b8  = pc[20];
            ar0 += a03.x*cr; ai0 += b03.x*ci;
            ar1 += a03.y*cr; ai1 += b03.y*ci;
            ar2 += a03.z*cr; ai2 += b03.z*ci;
            ar3 += a03.w*cr; ai3 += b03.w*ci;
            ar4 += a47.x*cr; ai4 += b47.x*ci;
            ar5 += a47.y*cr; ai5 += b47.y*ci;
            ar6 += a47.z*cr; ai6 += b47.z*ci;
            ar7 += a47.w*cr; ai7 += b47.w*ci;
            ar8 += a8 *cr;   ai8 += b8 *ci;
            float nr = cr*c - ci*s;                 // rotate for next h
            ci = cr*s + ci*c;
            cr = nr;
        }
        // h = 48 term: cos(pi f/2), sin(pi f/2) in {0, +-1}
        {
            const float2* r48 = &fadd[48][0];
            if (par == 0) {
                float cc = ((f & 3) == 0) ? 1.f : -1.f;
                ar0 += r48[0].x*cc; ar1 += r48[1].x*cc; ar2 += r48[2].x*cc;
                ar3 += r48[3].x*cc; ar4 += r48[4].x*cc; ar5 += r48[5].x*cc;
                ar6 += r48[6].x*cc; ar7 += r48[7].x*cc; ar8 += r48[8].x*cc;
            } else {
                float ss = ((f & 3) == 1) ? 1.f : -1.f;
                ai0 += r48[0].y*ss; ai1 += r48[1].y*ss; ai2 += r48[2].y*ss;
                ai3 += r48[3].y*ss; ai4 += r48[4].y*ss; ai5 += r48[5].y*ss;
                ai6 += r48[6].y*ss; ai7 += r48[7].y*ss; ai8 += r48[8].y*ss;
            }
        }
        float sgf = (par == 0) ? 1.f : -1.f;       // (-1)^f
        Xre[0][f] = x0s[0] + sgf*x96s[0] + ar0;  Xim[0][f] = -ai0;
        Xre[1][f] = x0s[1] + sgf*x96s[1] + ar1;  Xim[1][f] = -ai1;
        Xre[2][f] = x0s[2] + sgf*x96s[2] + ar2;  Xim[2][f] = -ai2;
        Xre[3][f] = x0s[3] + sgf*x96s[3] + ar3;  Xim[3][f] = -ai3;
        Xre[4][f] = x0s[4] + sgf*x96s[4] + ar4;  Xim[4][f] = -ai4;
        Xre[5][f] = x0s[5] + sgf*x96s[5] + ar5;  Xim[5][f] = -ai5;
        Xre[6][f] = x0s[6] + sgf*x96s[6] + ar6;  Xim[6][f] = -ai6;
        Xre[7][f] = x0s[7] + sgf*x96s[7] + ar7;  Xim[7][f] = -ai7;
        Xre[8][f] = x0s[8] + sgf*x96s[8] + ar8;  Xim[8][f] = -ai8;
    }
    __syncthreads();

    // mix_in = [lead_sum | diff_sum | self]  (re then im halves)
    for (int f = tid; f < FREQ; f += 128) {
        float yre = Xre[8][f], yim = Xim[8][f];
        float Are = 0.f, Aim = 0.f, Dre = 0.f, Dim = 0.f;
#pragma unroll
        for (int k = 0; k < Kk; k++) {
            float sre = Xre[k][f], sim = Xim[k][f];
            float fl = flt[k*FREQ + f];
            float fd = flt[(Kk + k)*FREQ + f];
            Are += sre*fl;          Aim += sim*fl;
            Dre += (sre - yre)*fd;  Dim += (sim - yim)*fd;
        }
        float fs = flt[2*Kk*FREQ + f];
        float* mo = &g_mixin[bc*KTOT];
        mo[f]                = Are;
        mo[FREQ + f]         = Dre;
        mo[2*FREQ + f]       = yre*fs;
        mo[MIXF + f]         = Aim;
        mo[MIXF + FREQ + f]  = Dim;
        mo[MIXF + 2*FREQ + f]= yim*fs;
    }
}

// ================= K4: mix_out = mix_in[582] @ V[582,194] + bias =================
#define K4_TN 128
#define K4_TM 32
#define K4_TK 32
__global__ void __launch_bounds__(128) k4(
                   const float* __restrict__ br, const float* __restrict__ bi)
{
    __shared__ float Vsh[K4_TK*K4_TN];   // 16 KB
    __shared__ float Ish[K4_TK*36];      // padded
    int tid = threadIdx.x;               // 128
    int n0 = blockIdx.x * K4_TN;
    int m0 = blockIdx.y * K4_TM;
    int on = n0 + tid;

    float accv[K4_TM];
#pragma unroll
    for (int m = 0; m < K4_TM; m++) accv[m] = 0.f;

    for (int kc = 0; kc < KTOT; kc += K4_TK) {
        __syncthreads();
        for (int kk = 0; kk < K4_TK; kk++) {
            int k = kc + kk;
            Vsh[kk*K4_TN + tid] = (k < KTOT && on < NOUT) ? g_V[k*NOUT + on] : 0.f;
        }
        for (int idx = tid; idx < K4_TM*K4_TK; idx += 128) {
            int m = idx / K4_TK, kk = idx % K4_TK;  // coalesced over kk
            int k = kc + kk;
            Ish[kk*36 + m] = (k < KTOT) ? g_mixin[(m0 + m)*KTOT + k] : 0.f;
        }
        __syncthreads();
        for (int kk = 0; kk < K4_TK; kk++) {
            float w = Vsh[kk*K4_TN + tid];
            const float4* ip = (const float4*)(&Ish[kk*36]);
#pragma unroll
            for (int mm = 0; mm < 8; mm++) {
                float4 iv = ip[mm];
                accv[4*mm+0] += iv.x * w;
                accv[4*mm+1] += iv.y * w;
                accv[4*mm+2] += iv.z * w;
                accv[4*mm+3] += iv.w * w;
            }
        }
    }
    if (on < NOUT) {
        float bias = (on < FREQ) ? br[on] : bi[on - FREQ];
#pragma unroll
        for (int m = 0; m < K4_TM; m++)
            g_mixout[(m0 + m)*NOUT + on] = accv[m] + bias;
    }
}

// ================= K5: irfft (double fold, 47-iter) + denormalize =================
__global__ void __launch_bounds__(192) k5()
{
    int bc = blockIdx.x;
    __shared__ float2 mo[FREQ];
    __shared__ float2 cb5[48][2];        // [f=1..47][parity of h]: (C, D)
    int tid = threadIdx.x;               // 192
    for (int i = tid; i < FREQ; i += 192)
        mo[i] = make_float2(g_mixout[bc*NOUT + i], g_mixout[bc*NOUT + FREQ + i]);
    __syncthreads();
    // pair (f, 96-f), f=1..47:
    for (int f = tid + 1; f <= 47; f += 192) {
        float2 X1 = mo[f], X2 = mo[96 - f];
        cb5[f][0] = make_float2(X1.x + X2.x, -X1.y + X2.y);
        cb5[f][1] = make_float2(X1.x - X2.x, -X1.y - X2.y);
    }
    __syncthreads();

    int h = tid;                          // one output sample per thread
    int par = h & 1;
    float c, s;
    sincospif(h * (1.0f/96.0f), &s, &c);  // angle 2*pi*h/192
    float cr = c, ci = s;                 // value at f=1
    float acc = 0.f;
#pragma unroll 47
    for (int f = 1; f <= 47; f++) {
        float2 CD = cb5[f][par];
        acc += CD.x*cr + CD.y*ci;         // C cos + D sin
        float nr = cr*c - ci*s;
        ci = cr*s + ci*c;
        cr = nr;
    }
    // f = 48 term: Xr48*cos(pi h/2) - Xi48*sin(pi h/2)
    {
        float2 X48 = mo[48];
        if (par == 0) acc += X48.x * (((h & 3) == 0) ? 1.f : -1.f);
        else          acc -= X48.y * (((h & 3) == 1) ? 1.f : -1.f);
    }
    float R0 = mo[0].x, R96 = mo[96].x;   // imag of DC/Nyquist ignored (pocketfft c2r)
    float xh = (R0 + ((par == 0) ? R96 : -R96) + 2.f*acc) * (1.f/Hh);
    float yn = g_seq[bc*SEQ + Ll + h];
    g_yout[(size_t)bc*Hh + h] = (yn + xh) * g_std[bc] + g_mu[bc];  // coalesced
}

// ================= K6: transpose yout (B,C,H) -> out (B,H,C) =================
__global__ void k6(float* __restrict__ out)
{
    __shared__ float tile[32][33];
    int b  = blockIdx.z;
    int c0 = blockIdx.x * 32, h0 = blockIdx.y * 32;
    int tx = threadIdx.x, ty = threadIdx.y;        // 32 x 8
#pragma unroll
    for (int y = 0; y < 32; y += 8) {
        int c = c0 + ty + y;
        if (c < Cc) tile[ty + y][tx] = g_yout[((size_t)b*Cc + c)*Hh + h0 + tx];
    }
    __syncthreads();
#pragma unroll
    for (int y = 0; y < 32; y += 8) {
        int c = c0 + tx, h = h0 + ty + y;
        if (c < Cc) out[((size_t)b*Hh + h)*Cc + c] = tile[tx][ty + y];
    }
}

// ================= launcher =================
extern "C" void kernel_launch(void* const* d_in, const int* in_sizes, int n_in,
                              void* d_out, int out_size)
{
    const float* x   = (const float*)d_in[0];
    const float* yh  = (const float*)d_in[1];
    const float* r   = (const float*)d_in[2];
    const float* tmp = (const float*)d_in[3];
    const float* cw  = (const float*)d_in[4];
    const float* bst = (const float*)d_in[5];
    const float* sb  = (const float*)d_in[6];
    const float* mhw = (const float*)d_in[7];
    const float* mhb = (const float*)d_in[8];
    const float* mwr = (const float*)d_in[9];
    const float* mwi = (const float*)d_in[10];
    const float* mbr = (const float*)d_in[11];
    const float* mbi = (const float*)d_in[12];
    const int*   lid = (const int*)d_in[13];
    const int*   shf = (const int*)d_in[14];
    float* out = (float*)d_out;

    float* gxt; cudaGetSymbolAddress((void**)&gxt, g_xt);
    float* gyt; cudaGetSymbolAddress((void**)&gyt, g_yt);

    dim3 tb(32, 8);
    ktr<<<dim3((Cc+31)/32, (Ll+31)/32, Bb), tb>>>(x,  gxt, Ll);     // launch 0
    ktr<<<dim3((Cc+31)/32, (Hh+31)/32, Bb), tb>>>(yh, gyt, Hh);     // launch 1
    k1<<<BC, 192>>>(r, tmp, cw, bst, sb);                           // launch 2
    k2<<<dim3((OUTD + K2_TN - 1)/K2_TN, BC/K2_TM), 128>>>(mhw, mhb);// launch 3 (profiled)
    k3<<<BC, 128>>>(lid, shf);                                      // launch 4
    k0<<<(KTOT*NOUT + 255)/256, 256>>>(mwr, mwi);                   // launch 5 (moved: only k4 needs g_V)
    k4<<<dim3((NOUT + K4_TN - 1)/K4_TN, BC/K4_TM), 128>>>(mbr, mbi);// launch 6
    k5<<<BC, 192>>>();                                              // launch 7
    k6<<<dim3((Cc+31)/32, Hh/32, Bb), tb>>>(out);                   // launch 8
}